// round 16
// baseline (speedup 1.0000x reference)
#include <cuda_runtime.h>
#include <cuda_fp16.h>
#include <float.h>
#include <math.h>
#include <stdint.h>

// ---------------- problem constants ----------------
#define T_TOK 8192
#define D_DIM 7168
#define E_EXP 256
#define N_GROUPS 8
#define TOPK_GROUPS 4
#define TOP_K 8

// ---------------- GEMM tiling ----------------
#define BM 128
#define BN 64
#define BK 64
#define NCHUNK (D_DIM / BK)      // 112
#define NTHREADS 512

// smem rows: 64 halves = 128 B data + 16 B pad = 144 B (conflict-free: 36-word stride)
#define ROW_B 144
#define A_SP_BYTES (128 * ROW_B)                 // 18432
#define B_SP_BYTES (64 * ROW_B)                  // 9216
#define A_OFF(st, sp) (((st) * 2 + (sp)) * A_SP_BYTES)
#define B_BASE (2 * 2 * A_SP_BYTES)              // 73728
#define B_OFF(st, sp) (B_BASE + ((st) * 2 + (sp)) * B_SP_BYTES)
#define SMEM_BYTES (B_BASE + 2 * 2 * B_SP_BYTES) // 110592

// piece scales: v ~= vh + vm*2^-11 (+ dropped ~2^-24 residual)
#define SC_UP1   2048.0f           // 2^11
#define SC_DN1   4.8828125e-4f     // 2^-11

// ---------------- device scratch ----------------
__device__ float g_scores[(size_t)T_TOK * E_EXP];     // sigmoid scores [T][E]
__device__ __half g_Bh[(size_t)E_EXP * D_DIM];        // W^T piece hi   [E][D]
__device__ __half g_Bm[(size_t)E_EXP * D_DIM];        // W^T piece mid (x 2^11)

// ---------------- PTX helpers ----------------
__device__ __forceinline__ uint32_t smem_u32(const void* p) {
    uint32_t a;
    asm("{ .reg .u64 t; cvta.to.shared.u64 t, %1; cvt.u32.u64 %0, t; }" : "=r"(a) : "l"(p));
    return a;
}
__device__ __forceinline__ void mma16816(float* c, const uint32_t* a, const uint32_t* b) {
    asm volatile(
        "mma.sync.aligned.m16n8k16.row.col.f32.f16.f16.f32 "
        "{%0,%1,%2,%3}, {%4,%5,%6,%7}, {%8,%9}, {%0,%1,%2,%3};"
        : "+f"(c[0]), "+f"(c[1]), "+f"(c[2]), "+f"(c[3])
        : "r"(a[0]), "r"(a[1]), "r"(a[2]), "r"(a[3]), "r"(b[0]), "r"(b[1]));
}
__device__ __forceinline__ void ldsm4(uint32_t& r0, uint32_t& r1, uint32_t& r2, uint32_t& r3,
                                      uint32_t addr) {
    asm volatile("ldmatrix.sync.aligned.m8n8.x4.shared.b16 {%0,%1,%2,%3}, [%4];"
                 : "=r"(r0), "=r"(r1), "=r"(r2), "=r"(r3) : "r"(addr));
}
__device__ __forceinline__ void cpasync16(uint32_t saddr, const void* g) {
    asm volatile("cp.async.cg.shared.global [%0], [%1], 16;" :: "r"(saddr), "l"(g));
}
#define CP_COMMIT() asm volatile("cp.async.commit_group;" ::: "memory")
#define CP_WAIT0()  asm volatile("cp.async.wait_group 0;" ::: "memory")

// 2-way split of two floats -> two packed fp16 pairs (elem0 in low 16 bits)
__device__ __forceinline__ void split2_2(float fx, float fy, uint32_t& h, uint32_t& m) {
    __half hx = __float2half_rn(fx), hy = __float2half_rn(fy);
    float rx = fx - __half2float(hx), ry = fy - __half2float(hy);
    __half mx = __float2half_rn(rx * SC_UP1), my = __float2half_rn(ry * SC_UP1);
    h = ((uint32_t)__half_as_ushort(hy) << 16) | (uint32_t)__half_as_ushort(hx);
    m = ((uint32_t)__half_as_ushort(my) << 16) | (uint32_t)__half_as_ushort(mx);
}

// ---------------------------------------------------------------------------
// W split + transpose: W[k][e] f32 -> g_Bh/g_Bm [e][k]
// ---------------------------------------------------------------------------
__global__ __launch_bounds__(256) void wsplit_kernel(const float* __restrict__ W) {
    __shared__ float tile[32][33];
    const int k0 = blockIdx.x * 32, e0 = blockIdx.y * 32;
    const int tx = threadIdx.x, ty = threadIdx.y;   // 32 x 8
#pragma unroll
    for (int i = 0; i < 4; i++)
        tile[ty + 8 * i][tx] = W[(size_t)(k0 + ty + 8 * i) * E_EXP + e0 + tx];
    __syncthreads();
#pragma unroll
    for (int i = 0; i < 4; i++) {
        const int e = e0 + ty + 8 * i;
        const int k = k0 + tx;
        float f = tile[tx][ty + 8 * i];
        __half h = __float2half_rn(f);
        float r1 = f - __half2float(h);
        __half m = __float2half_rn(r1 * SC_UP1);
        size_t o = (size_t)e * D_DIM + k;
        g_Bh[o] = h;
        g_Bm[o] = m;
    }
}

// ---------------------------------------------------------------------------
// GEMM: scores = sigmoid(x @ W), fp16x2-split mma.sync, 3 terms
// (hh + (hm+mh)*2^-11). Grid (4, 64) = 256 CTAs. CTA 128x64, 512 threads,
// 16 warps 4(M)x4(N), warp tile 32x16, BK=64 (112 sync rounds).
// ---------------------------------------------------------------------------
__global__ __launch_bounds__(NTHREADS, 1) void gemm_hmma3t_kernel(const float* __restrict__ x) {
    extern __shared__ char smc[];
    const uint32_t sb = smem_u32(smc);

    const int tid = threadIdx.x;
    const int lane = tid & 31, wid = tid >> 5;
    const int m0 = blockIdx.y * BM;
    const int n0 = blockIdx.x * BN;
    const int wm = (wid & 3) * 32;     // warp M offset
    const int wn = (wid >> 2) * 16;    // warp N offset
    const int g = lane >> 2;
    const int t = lane & 3;

    // ldmatrix per-lane offsets (bytes)
    const uint32_t laneA = (uint32_t)((lane & 15) * ROW_B + (lane >> 4) * 16);
    const uint32_t laneB = (uint32_t)(((lane & 7) + ((lane >> 4) & 1) * 8) * ROW_B +
                                      ((lane >> 3) & 1) * 16);

    float acc0[2][2][4], acc1[2][2][4];
#pragma unroll
    for (int i = 0; i < 2; i++)
#pragma unroll
        for (int j = 0; j < 2; j++)
#pragma unroll
            for (int q = 0; q < 4; q++) { acc0[i][j][q] = 0.0f; acc1[i][j][q] = 0.0f; }

    // ---- global load mappings ----
    // A: row = tid>>2 (0..127), 16 floats at koff = (tid&3)*16
    const int arow = tid >> 2;
    const int akoff = (tid & 3) * 16;
    const float* Ap = x + (size_t)(m0 + arow) * D_DIM + akoff;
    const uint32_t aDst = (uint32_t)(arow * ROW_B + akoff * 2);
    // B: row = tid>>3 (0..63), 16B seg = tid&7; each thread loads both pieces
    const int brow = tid >> 3;
    const int bseg = tid & 7;
    const __half* Bph = g_Bh + (size_t)(n0 + brow) * D_DIM + bseg * 8;
    const __half* Bpm = g_Bm + (size_t)(n0 + brow) * D_DIM + bseg * 8;
    const uint32_t bDst = (uint32_t)(brow * ROW_B + bseg * 16);

    // ---- helper: split 16 A floats to smem stage (uint4 stores) ----
    auto stsA = [&](int st, const float* src) {
#pragma unroll
        for (int jj = 0; jj < 2; jj++) {
            float4 v0 = ((const float4*)src)[2 * jj];
            float4 v1 = ((const float4*)src)[2 * jj + 1];
            uint32_t h0, m0_, h1, m1_, h2, m2_, h3, m3_;
            split2_2(v0.x, v0.y, h0, m0_);
            split2_2(v0.z, v0.w, h1, m1_);
            split2_2(v1.x, v1.y, h2, m2_);
            split2_2(v1.z, v1.w, h3, m3_);
            const uint32_t o = aDst + 16 * jj;
            *(uint4*)(smc + A_OFF(st, 0) + o) = make_uint4(h0, h1, h2, h3);
            *(uint4*)(smc + A_OFF(st, 1) + o) = make_uint4(m0_, m1_, m2_, m3_);
        }
    };

    // ---- prologue: chunk 0 into stage 0 ----
    {
        cpasync16(sb + B_OFF(0, 0) + bDst, Bph);
        cpasync16(sb + B_OFF(0, 1) + bDst, Bpm);
        CP_COMMIT();
        float a0[16];
#pragma unroll
        for (int j = 0; j < 4; j++) ((float4*)a0)[j] = ((const float4*)Ap)[j];
        stsA(0, a0);
        CP_WAIT0();
    }
    __syncthreads();

    float a_stage[16];

    for (int c = 0; c < NCHUNK; c++) {
        const int cur = c & 1, nxt = cur ^ 1;
        const bool has_next = (c + 1 < NCHUNK);
        if (has_next) {
            const int kn = (c + 1) * BK;
            cpasync16(sb + B_OFF(nxt, 0) + bDst, Bph + kn);
            cpasync16(sb + B_OFF(nxt, 1) + bDst, Bpm + kn);
            CP_COMMIT();
            const float4* ap4 = (const float4*)(Ap + kn);
#pragma unroll
            for (int j = 0; j < 4; j++) ((float4*)a_stage)[j] = ap4[j];
        }

        // ---- compute: 4 k16 steps from stage `cur` ----
#pragma unroll
        for (int ks = 0; ks < 4; ks++) {
            const uint32_t ko = (uint32_t)(ks * 32);
            const uint32_t aBase = sb + (uint32_t)(wm * ROW_B) + ko + laneA;
            const uint32_t bBase = sb + (uint32_t)(wn * ROW_B) + ko + laneB;

            uint32_t Ah[2][4], Am[2][4];
            uint32_t Bh[2][2], Bm[2][2];

            // hh
            ldsm4(Ah[0][0], Ah[0][1], Ah[0][2], Ah[0][3], aBase + A_OFF(cur, 0));
            ldsm4(Ah[1][0], Ah[1][1], Ah[1][2], Ah[1][3], aBase + A_OFF(cur, 0) + 16 * ROW_B);
            ldsm4(Bh[0][0], Bh[0][1], Bh[1][0], Bh[1][1], bBase + B_OFF(cur, 0));
#pragma unroll
            for (int mt = 0; mt < 2; mt++)
#pragma unroll
                for (int nt = 0; nt < 2; nt++) mma16816(acc0[mt][nt], Ah[mt], Bh[nt]);

            // hm
            ldsm4(Bm[0][0], Bm[0][1], Bm[1][0], Bm[1][1], bBase + B_OFF(cur, 1));
#pragma unroll
            for (int mt = 0; mt < 2; mt++)
#pragma unroll
                for (int nt = 0; nt < 2; nt++) mma16816(acc1[mt][nt], Ah[mt], Bm[nt]);

            // mh
            ldsm4(Am[0][0], Am[0][1], Am[0][2], Am[0][3], aBase + A_OFF(cur, 1));
            ldsm4(Am[1][0], Am[1][1], Am[1][2], Am[1][3], aBase + A_OFF(cur, 1) + 16 * ROW_B);
#pragma unroll
            for (int mt = 0; mt < 2; mt++)
#pragma unroll
                for (int nt = 0; nt < 2; nt++) mma16816(acc1[mt][nt], Am[mt], Bh[nt]);
        }

        if (has_next) {
            stsA(nxt, a_stage);
            CP_WAIT0();
        }
        __syncthreads();
    }

    // ---- epilogue: recombine scales, sigmoid, store ----
#pragma unroll
    for (int mt = 0; mt < 2; mt++) {
        const int r0 = m0 + wm + mt * 16 + g;
#pragma unroll
        for (int nt = 0; nt < 2; nt++) {
            const int cc = n0 + wn + nt * 8 + 2 * t;
            float z0 = fmaf(acc1[mt][nt][0], SC_DN1, acc0[mt][nt][0]);
            float z1 = fmaf(acc1[mt][nt][1], SC_DN1, acc0[mt][nt][1]);
            float z2 = fmaf(acc1[mt][nt][2], SC_DN1, acc0[mt][nt][2]);
            float z3 = fmaf(acc1[mt][nt][3], SC_DN1, acc0[mt][nt][3]);
            float2 v0, v1;
            v0.x = 1.0f / (1.0f + expf(-z0));
            v0.y = 1.0f / (1.0f + expf(-z1));
            v1.x = 1.0f / (1.0f + expf(-z2));
            v1.y = 1.0f / (1.0f + expf(-z3));
            *(float2*)(g_scores + (size_t)r0 * E_EXP + cc) = v0;
            *(float2*)(g_scores + (size_t)(r0 + 8) * E_EXP + cc) = v1;
        }
    }
}

// ---------------------------------------------------------------------------
// Routing: ONE WARP per token, zero block barriers. Lane owns 8 experts.
// Replicates jax top_k tie semantics (lowest index wins on equal values).
// ---------------------------------------------------------------------------
__global__ __launch_bounds__(256) void route_kernel(
    const float* __restrict__ bias, float* __restrict__ out, int write_indices) {
    const int lane = threadIdx.x & 31;
    const int tok = blockIdx.x * 8 + (threadIdx.x >> 5);

    // load 8 scores + 8 biased scores into registers
    const float* srow = g_scores + (size_t)tok * E_EXP + lane * 8;
    float4 a0 = *(const float4*)srow;
    float4 a1 = *(const float4*)(srow + 4);
    float4 b0 = *(const float4*)(bias + lane * 8);
    float4 b1 = *(const float4*)(bias + lane * 8 + 4);
    float sc[8] = {a0.x, a0.y, a0.z, a0.w, a1.x, a1.y, a1.z, a1.w};
    float s[8]  = {a0.x + b0.x, a0.y + b0.y, a0.z + b0.z, a0.w + b0.w,
                   a1.x + b1.x, a1.y + b1.y, a1.z + b1.z, a1.w + b1.w};

    // ---- group score: top2 within group of 32 experts (4 lanes) ----
    float t1 = -FLT_MAX, t2 = -FLT_MAX;
#pragma unroll
    for (int j = 0; j < 8; j++) {
        if (s[j] > t1) { t2 = t1; t1 = s[j]; }
        else if (s[j] > t2) t2 = s[j];
    }
#pragma unroll
    for (int off = 1; off <= 2; off <<= 1) {
        float o1 = __shfl_xor_sync(0xffffffffu, t1, off);
        float o2 = __shfl_xor_sync(0xffffffffu, t2, off);
        float hi = fmaxf(t1, o1);
        float lo = fmaxf(fminf(t1, o1), (t1 >= o1) ? t2 : o2);
        t1 = hi; t2 = lo;
    }
    const float gs = t1 + t2;   // group score (lanes of same group agree)

    // ---- top-4 groups (computed redundantly on every lane) ----
    float gsc[8];
#pragma unroll
    for (int gg = 0; gg < 8; gg++) gsc[gg] = __shfl_sync(0xffffffffu, gs, gg * 4);
    unsigned m = 0;
#pragma unroll
    for (int it = 0; it < TOPK_GROUPS; it++) {
        int best = 0; float bv = -FLT_MAX;
#pragma unroll
        for (int gg = 0; gg < 8; gg++)
            if (!((m >> gg) & 1u) && gsc[gg] > bv) { bv = gsc[gg]; best = gg; }
        m |= (1u << best);
    }
    const bool keep = (m >> (lane >> 2)) & 1u;

    float cur[8];
#pragma unroll
    for (int j = 0; j < 8; j++) cur[j] = keep ? s[j] : 0.0f;

    // ---- iterative top-8 (warp argmax, lowest-index tiebreak) ----
    float selw[8];
    int seli[8];
    float sum = 0.0f;
#pragma unroll
    for (int k = 0; k < TOP_K; k++) {
        float bv = cur[0]; int bj = 0;
#pragma unroll
        for (int j = 1; j < 8; j++)
            if (cur[j] > bv) { bv = cur[j]; bj = j; }
        int bidx = lane * 8 + bj;
#pragma unroll
        for (int off = 16; off; off >>= 1) {
            float ov = __shfl_xor_sync(0xffffffffu, bv, off);
            int oi = __shfl_xor_sync(0xffffffffu, bidx, off);
            if (ov > bv || (ov == bv && oi < bidx)) { bv = ov; bidx = oi; }
        }
        const int wl = bidx >> 3, wj = bidx & 7;
        float sv = 0.0f;
#pragma unroll
        for (int j = 0; j < 8; j++) if (wj == j) sv = sc[j];
        float w = __shfl_sync(0xffffffffu, sv, wl);
        selw[k] = w; seli[k] = bidx; sum += w;
        if (wl == lane) {
#pragma unroll
            for (int j = 0; j < 8; j++) if (j == wj) cur[j] = -FLT_MAX;
        }
    }

    // ---- normalize, scale, write (lane 0) ----
    if (lane == 0) {
        const float scale = 2.5f / (sum + 1e-20f);
        float* wrow = out + (size_t)tok * TOP_K;
        *(float4*)wrow = make_float4(selw[0] * scale, selw[1] * scale,
                                     selw[2] * scale, selw[3] * scale);
        *(float4*)(wrow + 4) = make_float4(selw[4] * scale, selw[5] * scale,
                                           selw[6] * scale, selw[7] * scale);
        if (write_indices) {
            float* irow = out + (size_t)T_TOK * TOP_K + (size_t)tok * TOP_K;
            *(float4*)irow = make_float4((float)seli[0], (float)seli[1],
                                         (float)seli[2], (float)seli[3]);
            *(float4*)(irow + 4) = make_float4((float)seli[4], (float)seli[5],
                                               (float)seli[6], (float)seli[7]);
        }
    }
}

// ---------------------------------------------------------------------------
extern "C" void kernel_launch(void* const* d_in, const int* in_sizes, int n_in,
                              void* d_out, int out_size) {
    const float* x = (const float*)d_in[0];
    const float* W = (const float*)d_in[1];
    const float* bias = (const float*)d_in[2];
    float* out = (float*)d_out;

    cudaFuncSetAttribute(gemm_hmma3t_kernel,
                         cudaFuncAttributeMaxDynamicSharedMemorySize, SMEM_BYTES);

    wsplit_kernel<<<dim3(D_DIM / 32, E_EXP / 32), dim3(32, 8)>>>(W);
    gemm_hmma3t_kernel<<<dim3(E_EXP / BN, T_TOK / BM), NTHREADS, SMEM_BYTES>>>(x);

    int write_indices = (out_size >= 2 * T_TOK * TOP_K) ? 1 : 0;
    route_kernel<<<T_TOK / 8, 256>>>(bias, out, write_indices);
}